// round 13
// baseline (speedup 1.0000x reference)
#include <cuda_runtime.h>
#include <math.h>

// ---------------- problem constants ----------------
#define BB   16
#define CC   256
#define HIM  56
#define HW   3136            // 56*56
#define TOK  (BB*HW)         // 50176
#define NHD  8               // heads
#define HDD  32              // head dim
#define NWT  49              // tokens per window (7*7)
#define WINS 1024            // B * 64 windows
#define MLPD 1024

// ---------------- scratch (device globals; no cudaMalloc allowed) ----------------
__device__ __align__(256) float g_y [TOK*CC];
__device__ __align__(256) float g_a [TOK*CC];
__device__ __align__(256) float g_a2[TOK*CC];
__device__ __align__(256) float g_q [TOK*CC];
__device__ __align__(256) float g_kv[TOK*2*CC];
__device__ __align__(256) float g_o [TOK*CC];
__device__ __align__(256) float g_h [TOK*MLPD];
__device__ __align__(256) float g_bias[NHD*NWT*NWT];

// ---------------- helpers ----------------
__device__ __forceinline__ unsigned totf32(float x) {
    unsigned r;
    asm("cvt.rna.tf32.f32 %0, %1;" : "=r"(r) : "f"(x));
    return r;
}

__device__ __forceinline__ void mma8(float& c0, float& c1, float& c2, float& c3,
                                     unsigned a0, unsigned a1, unsigned a2, unsigned a3,
                                     unsigned b0, unsigned b1) {
    asm("mma.sync.aligned.m16n8k8.row.col.f32.tf32.tf32.f32 "
        "{%0,%1,%2,%3},{%4,%5,%6,%7},{%8,%9},{%0,%1,%2,%3};"
        : "+f"(c0), "+f"(c1), "+f"(c2), "+f"(c3)
        : "r"(a0), "r"(a1), "r"(a2), "r"(a3), "r"(b0), "r"(b1));
}

// smem column swizzle: conflict-free for both transpose-stores (k varies by 4
// across lanes) and fragment loads (k varies by 1 across lanes).
__device__ __forceinline__ int swz(int k, int m) {
    return m ^ ((((k) & 3) ^ (((k) >> 2) & 3)) << 3);
}

__device__ __forceinline__ float gelu_exact(float x) {
    return 0.5f * x * (1.0f + erff(x * 0.70710678118654752f));
}

__device__ __forceinline__ float2 blockReduce2(float a, float b, float* red) {
    #pragma unroll
    for (int o = 16; o; o >>= 1) {
        a += __shfl_xor_sync(0xffffffffu, a, o);
        b += __shfl_xor_sync(0xffffffffu, b, o);
    }
    __syncthreads();
    int w = threadIdx.x >> 5;
    if ((threadIdx.x & 31) == 0) { red[w] = a; red[8 + w] = b; }
    __syncthreads();
    float ra = 0.f, rb = 0.f;
    #pragma unroll
    for (int i = 0; i < 8; i++) { ra += red[i]; rb += red[8 + i]; }
    return make_float2(ra, rb);
}

// Compute one 128x128x16 tile worth of MMAs from staged smem.
__device__ __forceinline__ void mma_tile(const unsigned (*As)[128], const unsigned (*Bs)[128],
                                         float c[2][8][4], int rowbase, int nbase,
                                         int gr, int gc) {
    #pragma unroll
    for (int ks = 0; ks < 2; ks++) {
        const int k0 = ks * 8;
        unsigned a[2][4];
        #pragma unroll
        for (int mi = 0; mi < 2; mi++) {
            int m0 = rowbase + mi * 16 + gr;
            a[mi][0] = As[k0 + gc    ][swz(k0 + gc,     m0)];
            a[mi][1] = As[k0 + gc    ][swz(k0 + gc,     m0 + 8)];
            a[mi][2] = As[k0 + gc + 4][swz(k0 + gc + 4, m0)];
            a[mi][3] = As[k0 + gc + 4][swz(k0 + gc + 4, m0 + 8)];
        }
        #pragma unroll
        for (int ni = 0; ni < 8; ni++) {
            int n0 = nbase + ni * 8 + gr;
            unsigned b0 = Bs[k0 + gc    ][swz(k0 + gc,     n0)];
            unsigned b1 = Bs[k0 + gc + 4][swz(k0 + gc + 4, n0)];
            mma8(c[0][ni][0], c[0][ni][1], c[0][ni][2], c[0][ni][3],
                 a[0][0], a[0][1], a[0][2], a[0][3], b0, b1);
            mma8(c[1][ni][0], c[1][ni][1], c[1][ni][2], c[1][ni][3],
                 a[1][0], a[1][1], a[1][2], a[1][3], b0, b1);
        }
    }
}

// ---------------- tf32 tensor-core GEMM: C[m,n] = A[m,:]·W[n,:] + bias[n] ----------------
// A row-major M x K, W row-major N x K. M,N multiples of 128, K multiple of 16.
// EPI: 0 = bias, 1 = bias + residual R, 2 = bias + exact GELU.
template<int EPI>
__global__ __launch_bounds__(256, 2) void gemm_tf32(
    const float* __restrict__ A, const float* __restrict__ W,
    const float* __restrict__ bias, const float* __restrict__ R,
    float* __restrict__ C, int Nn, int K)
{
    __shared__ __align__(16) unsigned As[16][128];
    __shared__ __align__(16) unsigned Bs[16][128];
    const int tid = threadIdx.x;
    const int nt = blockIdx.x * 128;
    const int mt = blockIdx.y * 128;
    const int lr = tid >> 2;           // 0..63
    const int lk = (tid & 3) * 4;      // 0,4,8,12
    const float* Ap0 = A + (size_t)(mt + lr)      * K + lk;
    const float* Ap1 = A + (size_t)(mt + lr + 64) * K + lk;
    const float* Wp0 = W + (size_t)(nt + lr)      * K + lk;
    const float* Wp1 = W + (size_t)(nt + lr + 64) * K + lk;

    const int lane = tid & 31;
    const int wid  = tid >> 5;
    const int gr = lane >> 2, gc = lane & 3;
    const int rowbase = (wid & 3) * 32;
    const int nbase   = (wid >> 2) * 64;

    float c[2][8][4];
    #pragma unroll
    for (int mi = 0; mi < 2; mi++)
        #pragma unroll
        for (int ni = 0; ni < 8; ni++)
            #pragma unroll
            for (int j = 0; j < 4; j++) c[mi][ni][j] = 0.f;

    float4 a0v = *(const float4*)Ap0;
    float4 a1v = *(const float4*)Ap1;
    float4 b0v = *(const float4*)Wp0;
    float4 b1v = *(const float4*)Wp1;

    for (int kt = 0; kt < K; kt += 16) {
        {
            float av0[4] = {a0v.x, a0v.y, a0v.z, a0v.w};
            float av1[4] = {a1v.x, a1v.y, a1v.z, a1v.w};
            float bv0[4] = {b0v.x, b0v.y, b0v.z, b0v.w};
            float bv1[4] = {b1v.x, b1v.y, b1v.z, b1v.w};
            #pragma unroll
            for (int i = 0; i < 4; i++) {
                As[lk + i][swz(lk + i, lr)]      = totf32(av0[i]);
                As[lk + i][swz(lk + i, lr + 64)] = totf32(av1[i]);
                Bs[lk + i][swz(lk + i, lr)]      = totf32(bv0[i]);
                Bs[lk + i][swz(lk + i, lr + 64)] = totf32(bv1[i]);
            }
        }
        __syncthreads();
        if (kt + 16 < K) {
            a0v = *(const float4*)(Ap0 + kt + 16);
            a1v = *(const float4*)(Ap1 + kt + 16);
            b0v = *(const float4*)(Wp0 + kt + 16);
            b1v = *(const float4*)(Wp1 + kt + 16);
        }
        mma_tile(As, Bs, c, rowbase, nbase, gr, gc);
        __syncthreads();
    }

    // epilogue: fragment (row, col) mapping for m16n8 f32 accumulators
    #pragma unroll
    for (int ni = 0; ni < 8; ni++) {
        int col = nt + nbase + ni * 8 + gc * 2;
        float2 bv = *(const float2*)(bias + col);
        #pragma unroll
        for (int mi = 0; mi < 2; mi++) {
            int r0 = mt + rowbase + mi * 16 + gr;
            float2 v0 = make_float2(c[mi][ni][0] + bv.x, c[mi][ni][1] + bv.y);
            float2 v1 = make_float2(c[mi][ni][2] + bv.x, c[mi][ni][3] + bv.y);
            size_t o0 = (size_t)r0 * Nn + col;
            size_t o1 = (size_t)(r0 + 8) * Nn + col;
            if (EPI == 1) {
                float2 r0v = *(const float2*)(R + o0);
                float2 r1v = *(const float2*)(R + o1);
                v0.x += r0v.x; v0.y += r0v.y;
                v1.x += r1v.x; v1.y += r1v.y;
            }
            if (EPI == 2) {
                v0.x = gelu_exact(v0.x); v0.y = gelu_exact(v0.y);
                v1.x = gelu_exact(v1.x); v1.y = gelu_exact(v1.y);
            }
            *(float2*)(C + o0) = v0;
            *(float2*)(C + o1) = v1;
        }
    }
}

// ---------------- embed GEMM (tf32): y[b*HW+m, n] = sum_k x[b,k,m]*pe_w[n,k] + pe_b[n] ----------
__global__ __launch_bounds__(256, 2) void gemm_embed_tf32(
    const float* __restrict__ X, const float* __restrict__ W,
    const float* __restrict__ bias, float* __restrict__ C)
{
    __shared__ __align__(16) unsigned As[16][128];
    __shared__ __align__(16) unsigned Bs[16][128];
    const int tid = threadIdx.x;
    const int nt = blockIdx.x * 128;
    const int mt = blockIdx.y * 128;
    const int b  = blockIdx.z;
    const float* A = X + (size_t)b * CC * HW;

    const int lkE = tid >> 4;          // 0..15
    const int lmE = (tid & 15) * 8;    // 0..120
    const bool mok = (mt + lmE) < HW;  // 8-runs entirely in/out (HW%8==0)
    const float* ApE = A + (size_t)lkE * HW + mt + lmE;
    const int xorA = (((lkE & 3) ^ ((lkE >> 2) & 3)) << 3);
    unsigned* dstA = &As[lkE][lmE ^ xorA];

    const int lr = tid >> 2;
    const int lk = (tid & 3) * 4;
    const float* Wp0 = W + (size_t)(nt + lr)      * CC + lk;
    const float* Wp1 = W + (size_t)(nt + lr + 64) * CC + lk;

    const int lane = tid & 31;
    const int wid  = tid >> 5;
    const int gr = lane >> 2, gc = lane & 3;
    const int rowbase = (wid & 3) * 32;
    const int nbase   = (wid >> 2) * 64;

    float c[2][8][4];
    #pragma unroll
    for (int mi = 0; mi < 2; mi++)
        #pragma unroll
        for (int ni = 0; ni < 8; ni++)
            #pragma unroll
            for (int j = 0; j < 4; j++) c[mi][ni][j] = 0.f;

    const float4 z4 = make_float4(0.f, 0.f, 0.f, 0.f);
    float4 a0v = mok ? *(const float4*)(ApE)     : z4;
    float4 a1v = mok ? *(const float4*)(ApE + 4) : z4;
    float4 b0v = *(const float4*)Wp0;
    float4 b1v = *(const float4*)Wp1;

    for (int kt = 0; kt < CC; kt += 16) {
        {
            uint4 u0 = make_uint4(totf32(a0v.x), totf32(a0v.y), totf32(a0v.z), totf32(a0v.w));
            uint4 u1 = make_uint4(totf32(a1v.x), totf32(a1v.y), totf32(a1v.z), totf32(a1v.w));
            *(uint4*)dstA       = u0;
            *(uint4*)(dstA + 4) = u1;
            float bv0[4] = {b0v.x, b0v.y, b0v.z, b0v.w};
            float bv1[4] = {b1v.x, b1v.y, b1v.z, b1v.w};
            #pragma unroll
            for (int i = 0; i < 4; i++) {
                Bs[lk + i][swz(lk + i, lr)]      = totf32(bv0[i]);
                Bs[lk + i][swz(lk + i, lr + 64)] = totf32(bv1[i]);
            }
        }
        __syncthreads();
        if (kt + 16 < CC) {
            a0v = mok ? *(const float4*)(ApE + (size_t)(kt + 16) * HW)     : z4;
            a1v = mok ? *(const float4*)(ApE + (size_t)(kt + 16) * HW + 4) : z4;
            b0v = *(const float4*)(Wp0 + kt + 16);
            b1v = *(const float4*)(Wp1 + kt + 16);
        }
        mma_tile(As, Bs, c, rowbase, nbase, gr, gc);
        __syncthreads();
    }

    #pragma unroll
    for (int ni = 0; ni < 8; ni++) {
        int col = nt + nbase + ni * 8 + gc * 2;
        float2 bv = *(const float2*)(bias + col);
        #pragma unroll
        for (int mi = 0; mi < 2; mi++) {
            int mr0 = mt + rowbase + mi * 16 + gr;
            if (mr0 < HW) {
                float2 v0 = make_float2(c[mi][ni][0] + bv.x, c[mi][ni][1] + bv.y);
                *(float2*)(C + ((size_t)b * HW + mr0) * CC + col) = v0;
            }
            if (mr0 + 8 < HW) {
                float2 v1 = make_float2(c[mi][ni][2] + bv.x, c[mi][ni][3] + bv.y);
                *(float2*)(C + ((size_t)b * HW + mr0 + 8) * CC + col) = v1;
            }
        }
    }
}

// ---------------- fused double LayerNorm (pe_ln then n1) ----------------
__global__ __launch_bounds__(256) void dual_ln(
    const float* __restrict__ in,
    const float* __restrict__ w1, const float* __restrict__ b1,
    const float* __restrict__ w2, const float* __restrict__ b2,
    float* __restrict__ yOut, float* __restrict__ aOut)
{
    __shared__ float red[16];
    const size_t t = blockIdx.x;
    const int c = threadIdx.x;
    float v = in[t * CC + c];
    float2 s = blockReduce2(v, v * v, red);
    float mean = s.x * (1.f / CC);
    float var  = s.y * (1.f / CC) - mean * mean;
    float y = (v - mean) * rsqrtf(var + 1e-5f) * w1[c] + b1[c];
    if (yOut) yOut[t * CC + c] = y;
    float2 s2 = blockReduce2(y, y * y, red);
    float mean2 = s2.x * (1.f / CC);
    float var2  = s2.y * (1.f / CC) - mean2 * mean2;
    aOut[t * CC + c] = (y - mean2) * rsqrtf(var2 + 1e-5f) * w2[c] + b2[c];
}

__global__ __launch_bounds__(256) void ln_single(
    const float* __restrict__ in,
    const float* __restrict__ w, const float* __restrict__ b,
    float* __restrict__ outp)
{
    __shared__ float red[16];
    const size_t t = blockIdx.x;
    const int c = threadIdx.x;
    float v = in[t * CC + c];
    float2 s = blockReduce2(v, v * v, red);
    float mean = s.x * (1.f / CC);
    float var  = s.y * (1.f / CC) - mean * mean;
    outp[t * CC + c] = (v - mean) * rsqrtf(var + 1e-5f) * w[c] + b[c];
}

// ---------------- relative position bias expand: (NH, 49, 49) ----------------
__global__ void bias_kernel(const float* __restrict__ rel, float* __restrict__ bout)
{
    int idx = blockIdx.x * blockDim.x + threadIdx.x;
    if (idx >= NHD * NWT * NWT) return;
    int h  = idx / (NWT * NWT);
    int pq = idx % (NWT * NWT);
    int p = pq / NWT, q = pq % NWT;
    int i1 = p / 7, j1 = p % 7, i2 = q / 7, j2 = q % 7;
    int ridx = (i1 - i2 + 6) * 13 + (j1 - j2 + 6);
    bout[idx] = rel[ridx * NHD + h];
}

// ---------------- windowed attention: per (window, head) ----------------
__global__ __launch_bounds__(64) void attn_kernel(
    const float* __restrict__ q, const float* __restrict__ kv,
    const float* __restrict__ bias, float* __restrict__ o)
{
    __shared__ __align__(16) float qs[NWT * 32];
    __shared__ __align__(16) float ks[NWT * 32];
    __shared__ __align__(16) float vs[NWT * 32];
    __shared__ float ss[NWT * 51];
    const int tid  = threadIdx.x;
    const int win  = blockIdx.x;
    const int head = blockIdx.y;
    const int b  = win >> 6;
    const int w6 = win & 63;
    const int t0 = b * HW + (w6 >> 3) * 7 * HIM + (w6 & 7) * 7;

    for (int idx = tid; idx < NWT * 32; idx += 64) {
        int n = idx >> 5, d = idx & 31;
        int t = t0 + (n / 7) * HIM + (n % 7);
        qs[idx] = q [(size_t)t * CC + head * 32 + d];
        ks[idx] = kv[(size_t)t * (2*CC) + head * 32 + d];
        vs[idx] = kv[(size_t)t * (2*CC) + CC + head * 32 + d];
    }
    __syncthreads();

    const int r = tid;
    if (r < NWT) {
        float4 qr[8];
        #pragma unroll
        for (int i = 0; i < 8; i++) qr[i] = ((const float4*)(qs + r * 32))[i];
        const float* brow = bias + head * (NWT * NWT) + r * NWT;
        float mx = -1e30f;
        for (int c = 0; c < NWT; c++) {
            const float4* kp = (const float4*)(ks + c * 32);
            float acc = 0.f;
            #pragma unroll
            for (int i = 0; i < 8; i++) {
                float4 kk = kp[i];
                acc += qr[i].x * kk.x + qr[i].y * kk.y + qr[i].z * kk.z + qr[i].w * kk.w;
            }
            float s = acc * 0.17677669529663687f + brow[c];
            ss[r * 51 + c] = s;
            mx = fmaxf(mx, s);
        }
        float sum = 0.f;
        for (int c = 0; c < NWT; c++) {
            float e = __expf(ss[r * 51 + c] - mx);
            ss[r * 51 + c] = e;
            sum += e;
        }
        float inv = 1.f / sum;
        float4 oa[8];
        #pragma unroll
        for (int i = 0; i < 8; i++) oa[i] = make_float4(0.f, 0.f, 0.f, 0.f);
        for (int c = 0; c < NWT; c++) {
            float p = ss[r * 51 + c];
            const float4* vp = (const float4*)(vs + c * 32);
            #pragma unroll
            for (int i = 0; i < 8; i++) {
                float4 vv = vp[i];
                oa[i].x += p * vv.x; oa[i].y += p * vv.y;
                oa[i].z += p * vv.z; oa[i].w += p * vv.w;
            }
        }
        int t = t0 + (r / 7) * HIM + (r % 7);
        float4* op = (float4*)(o + (size_t)t * CC + head * 32);
        #pragma unroll
        for (int i = 0; i < 8; i++) {
            oa[i].x *= inv; oa[i].y *= inv; oa[i].z *= inv; oa[i].w *= inv;
            op[i] = oa[i];
        }
    }
}

// ---------------- (B, HW, C) -> (B, C, HW) transpose ----------------
__global__ void transpose_out(const float* __restrict__ in, float* __restrict__ out)
{
    __shared__ float tile[32][33];
    const int b   = blockIdx.z;
    const int hw0 = blockIdx.x * 32;
    const int c0  = blockIdx.y * 32;
    #pragma unroll
    for (int i = 0; i < 4; i++) {
        int r = threadIdx.y + i * 8;
        tile[r][threadIdx.x] = in[((size_t)b * HW + hw0 + r) * CC + c0 + threadIdx.x];
    }
    __syncthreads();
    #pragma unroll
    for (int i = 0; i < 4; i++) {
        int r = threadIdx.y + i * 8;
        out[(size_t)b * CC * HW + (size_t)(c0 + r) * HW + hw0 + threadIdx.x] = tile[threadIdx.x][r];
    }
}

// ---------------- launch ----------------
extern "C" void kernel_launch(void* const* d_in, const int* in_sizes, int n_in,
                              void* d_out, int out_size)
{
    const float* x1      = (const float*)d_in[0];
    const float* x2      = (const float*)d_in[1];
    const float* pe_w    = (const float*)d_in[2];
    const float* pe_b    = (const float*)d_in[3];
    const float* pe_ln_w = (const float*)d_in[4];
    const float* pe_ln_b = (const float*)d_in[5];
    const float* n1_w    = (const float*)d_in[6];
    const float* n1_b    = (const float*)d_in[7];
    const float* q_w     = (const float*)d_in[8];
    const float* q_b     = (const float*)d_in[9];
    const float* kv_w    = (const float*)d_in[10];
    const float* kv_b    = (const float*)d_in[11];
    const float* relb    = (const float*)d_in[12];
    const float* proj_w  = (const float*)d_in[13];
    const float* proj_b  = (const float*)d_in[14];
    const float* n2_w    = (const float*)d_in[15];
    const float* n2_b    = (const float*)d_in[16];
    const float* fc1_w   = (const float*)d_in[17];
    const float* fc1_b   = (const float*)d_in[18];
    const float* fc2_w   = (const float*)d_in[19];
    const float* fc2_b   = (const float*)d_in[20];
    float* out = (float*)d_out;

    float *y, *a, *a2, *qb, *kvb, *ob, *hb, *bb;
    cudaGetSymbolAddress((void**)&y,  g_y);
    cudaGetSymbolAddress((void**)&a,  g_a);
    cudaGetSymbolAddress((void**)&a2, g_a2);
    cudaGetSymbolAddress((void**)&qb, g_q);
    cudaGetSymbolAddress((void**)&kvb,g_kv);
    cudaGetSymbolAddress((void**)&ob, g_o);
    cudaGetSymbolAddress((void**)&hb, g_h);
    cudaGetSymbolAddress((void**)&bb, g_bias);

    // embed x1 -> pre (ob), fused pe_ln + n1 -> y (shortcut), a (attn input)
    gemm_embed_tf32<<<dim3(2, 25, BB), 256>>>(x1, pe_w, pe_b, ob);
    dual_ln<<<TOK, 256>>>(ob, pe_ln_w, pe_ln_b, n1_w, n1_b, y, a);
    // embed x2 -> pre (ob), fused LNs -> a2 only
    gemm_embed_tf32<<<dim3(2, 25, BB), 256>>>(x2, pe_w, pe_b, ob);
    dual_ln<<<TOK, 256>>>(ob, pe_ln_w, pe_ln_b, n1_w, n1_b, nullptr, a2);

    // q / kv projections
    gemm_tf32<0><<<dim3(2, TOK/128), 256>>>(a,  q_w,  q_b,  nullptr, qb,  CC,   CC);
    gemm_tf32<0><<<dim3(4, TOK/128), 256>>>(a2, kv_w, kv_b, nullptr, kvb, 2*CC, CC);

    // relative position bias + attention
    bias_kernel<<<(NHD*NWT*NWT + 255)/256, 256>>>(relb, bb);
    attn_kernel<<<dim3(WINS, NHD), 64>>>(qb, kvb, bb, ob);

    // proj with residual (in-place on y)
    gemm_tf32<1><<<dim3(2, TOK/128), 256>>>(ob, proj_w, proj_b, y, y, CC, CC);

    // MLP: LN -> fc1+GELU -> fc2 + residual
    ln_single<<<TOK, 256>>>(y, n2_w, n2_b, a);
    gemm_tf32<2><<<dim3(8, TOK/128), 256>>>(a,  fc1_w, fc1_b, nullptr, hb, MLPD, CC);
    gemm_tf32<1><<<dim3(2, TOK/128), 256>>>(hb, fc2_w, fc2_b, y, ob, CC, MLPD);

    // (B, HW, C) -> (B, C, H, W)
    transpose_out<<<dim3(HW/32, CC/32, BB), dim3(32, 8)>>>(ob, out);
}

// round 14
// speedup vs baseline: 1.0013x; 1.0013x over previous
#include <cuda_runtime.h>
#include <math.h>

// ---------------- problem constants ----------------
#define BB   16
#define CC   256
#define HIM  56
#define HW   3136            // 56*56
#define TOK  (BB*HW)         // 50176
#define NHD  8               // heads
#define HDD  32              // head dim
#define NWT  49              // tokens per window (7*7)
#define WINS 1024            // B * 64 windows
#define MLPD 1024

// ---------------- scratch (device globals; no cudaMalloc allowed) ----------------
__device__ __align__(256) float g_y [TOK*CC];
__device__ __align__(256) float g_a [TOK*CC];
__device__ __align__(256) float g_a2[TOK*CC];
__device__ __align__(256) float g_q [TOK*CC];
__device__ __align__(256) float g_kv[TOK*2*CC];
__device__ __align__(256) float g_o [TOK*CC];
__device__ __align__(256) float g_h [TOK*MLPD];
__device__ __align__(256) float g_bias[NHD*NWT*NWT];

// ---------------- helpers ----------------
__device__ __forceinline__ unsigned totf32(float x) {
    unsigned r;
    asm("cvt.rna.tf32.f32 %0, %1;" : "=r"(r) : "f"(x));
    return r;
}

__device__ __forceinline__ void mma8(float& c0, float& c1, float& c2, float& c3,
                                     unsigned a0, unsigned a1, unsigned a2, unsigned a3,
                                     unsigned b0, unsigned b1) {
    asm("mma.sync.aligned.m16n8k8.row.col.f32.tf32.tf32.f32 "
        "{%0,%1,%2,%3},{%4,%5,%6,%7},{%8,%9},{%0,%1,%2,%3};"
        : "+f"(c0), "+f"(c1), "+f"(c2), "+f"(c3)
        : "r"(a0), "r"(a1), "r"(a2), "r"(a3), "r"(b0), "r"(b1));
}

// smem column swizzle: conflict-free for both transpose-stores (k varies by 4
// across lanes) and fragment loads (k varies by 1 across lanes).
__device__ __forceinline__ int swz(int k, int m) {
    return m ^ ((((k) & 3) ^ (((k) >> 2) & 3)) << 3);
}

__device__ __forceinline__ float gelu_exact(float x) {
    return 0.5f * x * (1.0f + erff(x * 0.70710678118654752f));
}

__device__ __forceinline__ float2 blockReduce2(float a, float b, float* red) {
    #pragma unroll
    for (int o = 16; o; o >>= 1) {
        a += __shfl_xor_sync(0xffffffffu, a, o);
        b += __shfl_xor_sync(0xffffffffu, b, o);
    }
    __syncthreads();
    int w = threadIdx.x >> 5;
    if ((threadIdx.x & 31) == 0) { red[w] = a; red[8 + w] = b; }
    __syncthreads();
    float ra = 0.f, rb = 0.f;
    #pragma unroll
    for (int i = 0; i < 8; i++) { ra += red[i]; rb += red[8 + i]; }
    return make_float2(ra, rb);
}

// Compute one 128x128x16 tile worth of MMAs from staged smem.
__device__ __forceinline__ void mma_tile(const unsigned (*As)[128], const unsigned (*Bs)[128],
                                         float c[2][8][4], int rowbase, int nbase,
                                         int gr, int gc) {
    #pragma unroll
    for (int ks = 0; ks < 2; ks++) {
        const int k0 = ks * 8;
        unsigned a[2][4];
        #pragma unroll
        for (int mi = 0; mi < 2; mi++) {
            int m0 = rowbase + mi * 16 + gr;
            a[mi][0] = As[k0 + gc    ][swz(k0 + gc,     m0)];
            a[mi][1] = As[k0 + gc    ][swz(k0 + gc,     m0 + 8)];
            a[mi][2] = As[k0 + gc + 4][swz(k0 + gc + 4, m0)];
            a[mi][3] = As[k0 + gc + 4][swz(k0 + gc + 4, m0 + 8)];
        }
        #pragma unroll
        for (int ni = 0; ni < 8; ni++) {
            int n0 = nbase + ni * 8 + gr;
            unsigned b0 = Bs[k0 + gc    ][swz(k0 + gc,     n0)];
            unsigned b1 = Bs[k0 + gc + 4][swz(k0 + gc + 4, n0)];
            mma8(c[0][ni][0], c[0][ni][1], c[0][ni][2], c[0][ni][3],
                 a[0][0], a[0][1], a[0][2], a[0][3], b0, b1);
            mma8(c[1][ni][0], c[1][ni][1], c[1][ni][2], c[1][ni][3],
                 a[1][0], a[1][1], a[1][2], a[1][3], b0, b1);
        }
    }
}

// ---------------- tf32 tensor-core GEMM: C[m,n] = A[m,:]·W[n,:] + bias[n] ----------------
// A row-major M x K, W row-major N x K. M,N multiples of 128, K multiple of 16.
// EPI: 0 = bias, 1 = bias + residual R, 2 = bias + exact GELU.
template<int EPI>
__global__ __launch_bounds__(256, 2) void gemm_tf32(
    const float* __restrict__ A, const float* __restrict__ W,
    const float* __restrict__ bias, const float* __restrict__ R,
    float* __restrict__ C, int Nn, int K)
{
    __shared__ __align__(16) unsigned As[16][128];
    __shared__ __align__(16) unsigned Bs[16][128];
    const int tid = threadIdx.x;
    const int nt = blockIdx.x * 128;
    const int mt = blockIdx.y * 128;
    const int lr = tid >> 2;           // 0..63
    const int lk = (tid & 3) * 4;      // 0,4,8,12
    const float* Ap0 = A + (size_t)(mt + lr)      * K + lk;
    const float* Ap1 = A + (size_t)(mt + lr + 64) * K + lk;
    const float* Wp0 = W + (size_t)(nt + lr)      * K + lk;
    const float* Wp1 = W + (size_t)(nt + lr + 64) * K + lk;

    const int lane = tid & 31;
    const int wid  = tid >> 5;
    const int gr = lane >> 2, gc = lane & 3;
    const int rowbase = (wid & 3) * 32;
    const int nbase   = (wid >> 2) * 64;

    float c[2][8][4];
    #pragma unroll
    for (int mi = 0; mi < 2; mi++)
        #pragma unroll
        for (int ni = 0; ni < 8; ni++)
            #pragma unroll
            for (int j = 0; j < 4; j++) c[mi][ni][j] = 0.f;

    float4 a0v = *(const float4*)Ap0;
    float4 a1v = *(const float4*)Ap1;
    float4 b0v = *(const float4*)Wp0;
    float4 b1v = *(const float4*)Wp1;

    for (int kt = 0; kt < K; kt += 16) {
        {
            float av0[4] = {a0v.x, a0v.y, a0v.z, a0v.w};
            float av1[4] = {a1v.x, a1v.y, a1v.z, a1v.w};
            float bv0[4] = {b0v.x, b0v.y, b0v.z, b0v.w};
            float bv1[4] = {b1v.x, b1v.y, b1v.z, b1v.w};
            #pragma unroll
            for (int i = 0; i < 4; i++) {
                As[lk + i][swz(lk + i, lr)]      = totf32(av0[i]);
                As[lk + i][swz(lk + i, lr + 64)] = totf32(av1[i]);
                Bs[lk + i][swz(lk + i, lr)]      = totf32(bv0[i]);
                Bs[lk + i][swz(lk + i, lr + 64)] = totf32(bv1[i]);
            }
        }
        __syncthreads();
        if (kt + 16 < K) {
            a0v = *(const float4*)(Ap0 + kt + 16);
            a1v = *(const float4*)(Ap1 + kt + 16);
            b0v = *(const float4*)(Wp0 + kt + 16);
            b1v = *(const float4*)(Wp1 + kt + 16);
        }
        mma_tile(As, Bs, c, rowbase, nbase, gr, gc);
        __syncthreads();
    }

    // epilogue: fragment (row, col) mapping for m16n8 f32 accumulators
    #pragma unroll
    for (int ni = 0; ni < 8; ni++) {
        int col = nt + nbase + ni * 8 + gc * 2;
        float2 bv = *(const float2*)(bias + col);
        #pragma unroll
        for (int mi = 0; mi < 2; mi++) {
            int r0 = mt + rowbase + mi * 16 + gr;
            float2 v0 = make_float2(c[mi][ni][0] + bv.x, c[mi][ni][1] + bv.y);
            float2 v1 = make_float2(c[mi][ni][2] + bv.x, c[mi][ni][3] + bv.y);
            size_t o0 = (size_t)r0 * Nn + col;
            size_t o1 = (size_t)(r0 + 8) * Nn + col;
            if (EPI == 1) {
                float2 r0v = *(const float2*)(R + o0);
                float2 r1v = *(const float2*)(R + o1);
                v0.x += r0v.x; v0.y += r0v.y;
                v1.x += r1v.x; v1.y += r1v.y;
            }
            if (EPI == 2) {
                v0.x = gelu_exact(v0.x); v0.y = gelu_exact(v0.y);
                v1.x = gelu_exact(v1.x); v1.y = gelu_exact(v1.y);
            }
            *(float2*)(C + o0) = v0;
            *(float2*)(C + o1) = v1;
        }
    }
}

// ---------------- embed GEMM (tf32): y[b*HW+m, n] = sum_k x[b,k,m]*pe_w[n,k] + pe_b[n] ----------
__global__ __launch_bounds__(256, 2) void gemm_embed_tf32(
    const float* __restrict__ X, const float* __restrict__ W,
    const float* __restrict__ bias, float* __restrict__ C)
{
    __shared__ __align__(16) unsigned As[16][128];
    __shared__ __align__(16) unsigned Bs[16][128];
    const int tid = threadIdx.x;
    const int nt = blockIdx.x * 128;
    const int mt = blockIdx.y * 128;
    const int b  = blockIdx.z;
    const float* A = X + (size_t)b * CC * HW;

    const int lkE = tid >> 4;          // 0..15
    const int lmE = (tid & 15) * 8;    // 0..120
    const bool mok = (mt + lmE) < HW;  // 8-runs entirely in/out (HW%8==0)
    const float* ApE = A + (size_t)lkE * HW + mt + lmE;
    const int xorA = (((lkE & 3) ^ ((lkE >> 2) & 3)) << 3);
    unsigned* dstA = &As[lkE][lmE ^ xorA];

    const int lr = tid >> 2;
    const int lk = (tid & 3) * 4;
    const float* Wp0 = W + (size_t)(nt + lr)      * CC + lk;
    const float* Wp1 = W + (size_t)(nt + lr + 64) * CC + lk;

    const int lane = tid & 31;
    const int wid  = tid >> 5;
    const int gr = lane >> 2, gc = lane & 3;
    const int rowbase = (wid & 3) * 32;
    const int nbase   = (wid >> 2) * 64;

    float c[2][8][4];
    #pragma unroll
    for (int mi = 0; mi < 2; mi++)
        #pragma unroll
        for (int ni = 0; ni < 8; ni++)
            #pragma unroll
            for (int j = 0; j < 4; j++) c[mi][ni][j] = 0.f;

    const float4 z4 = make_float4(0.f, 0.f, 0.f, 0.f);
    float4 a0v = mok ? *(const float4*)(ApE)     : z4;
    float4 a1v = mok ? *(const float4*)(ApE + 4) : z4;
    float4 b0v = *(const float4*)Wp0;
    float4 b1v = *(const float4*)Wp1;

    for (int kt = 0; kt < CC; kt += 16) {
        {
            uint4 u0 = make_uint4(totf32(a0v.x), totf32(a0v.y), totf32(a0v.z), totf32(a0v.w));
            uint4 u1 = make_uint4(totf32(a1v.x), totf32(a1v.y), totf32(a1v.z), totf32(a1v.w));
            *(uint4*)dstA       = u0;
            *(uint4*)(dstA + 4) = u1;
            float bv0[4] = {b0v.x, b0v.y, b0v.z, b0v.w};
            float bv1[4] = {b1v.x, b1v.y, b1v.z, b1v.w};
            #pragma unroll
            for (int i = 0; i < 4; i++) {
                Bs[lk + i][swz(lk + i, lr)]      = totf32(bv0[i]);
                Bs[lk + i][swz(lk + i, lr + 64)] = totf32(bv1[i]);
            }
        }
        __syncthreads();
        if (kt + 16 < CC) {
            a0v = mok ? *(const float4*)(ApE + (size_t)(kt + 16) * HW)     : z4;
            a1v = mok ? *(const float4*)(ApE + (size_t)(kt + 16) * HW + 4) : z4;
            b0v = *(const float4*)(Wp0 + kt + 16);
            b1v = *(const float4*)(Wp1 + kt + 16);
        }
        mma_tile(As, Bs, c, rowbase, nbase, gr, gc);
        __syncthreads();
    }

    #pragma unroll
    for (int ni = 0; ni < 8; ni++) {
        int col = nt + nbase + ni * 8 + gc * 2;
        float2 bv = *(const float2*)(bias + col);
        #pragma unroll
        for (int mi = 0; mi < 2; mi++) {
            int mr0 = mt + rowbase + mi * 16 + gr;
            if (mr0 < HW) {
                float2 v0 = make_float2(c[mi][ni][0] + bv.x, c[mi][ni][1] + bv.y);
                *(float2*)(C + ((size_t)b * HW + mr0) * CC + col) = v0;
            }
            if (mr0 + 8 < HW) {
                float2 v1 = make_float2(c[mi][ni][2] + bv.x, c[mi][ni][3] + bv.y);
                *(float2*)(C + ((size_t)b * HW + mr0 + 8) * CC + col) = v1;
            }
        }
    }
}

// ---------------- fused double LayerNorm (pe_ln then n1) ----------------
__global__ __launch_bounds__(256) void dual_ln(
    const float* __restrict__ in,
    const float* __restrict__ w1, const float* __restrict__ b1,
    const float* __restrict__ w2, const float* __restrict__ b2,
    float* __restrict__ yOut, float* __restrict__ aOut)
{
    __shared__ float red[16];
    const size_t t = blockIdx.x;
    const int c = threadIdx.x;
    float v = in[t * CC + c];
    float2 s = blockReduce2(v, v * v, red);
    float mean = s.x * (1.f / CC);
    float var  = s.y * (1.f / CC) - mean * mean;
    float y = (v - mean) * rsqrtf(var + 1e-5f) * w1[c] + b1[c];
    if (yOut) yOut[t * CC + c] = y;
    float2 s2 = blockReduce2(y, y * y, red);
    float mean2 = s2.x * (1.f / CC);
    float var2  = s2.y * (1.f / CC) - mean2 * mean2;
    aOut[t * CC + c] = (y - mean2) * rsqrtf(var2 + 1e-5f) * w2[c] + b2[c];
}

__global__ __launch_bounds__(256) void ln_single(
    const float* __restrict__ in,
    const float* __restrict__ w, const float* __restrict__ b,
    float* __restrict__ outp)
{
    __shared__ float red[16];
    const size_t t = blockIdx.x;
    const int c = threadIdx.x;
    float v = in[t * CC + c];
    float2 s = blockReduce2(v, v * v, red);
    float mean = s.x * (1.f / CC);
    float var  = s.y * (1.f / CC) - mean * mean;
    outp[t * CC + c] = (v - mean) * rsqrtf(var + 1e-5f) * w[c] + b[c];
}

// ---------------- relative position bias expand: (NH, 49, 49) ----------------
__global__ void bias_kernel(const float* __restrict__ rel, float* __restrict__ bout)
{
    int idx = blockIdx.x * blockDim.x + threadIdx.x;
    if (idx >= NHD * NWT * NWT) return;
    int h  = idx / (NWT * NWT);
    int pq = idx % (NWT * NWT);
    int p = pq / NWT, q = pq % NWT;
    int i1 = p / 7, j1 = p % 7, i2 = q / 7, j2 = q % 7;
    int ridx = (i1 - i2 + 6) * 13 + (j1 - j2 + 6);
    bout[idx] = rel[ridx * NHD + h];
}

// ---------------- windowed attention: per (window, head) ----------------
__global__ __launch_bounds__(64) void attn_kernel(
    const float* __restrict__ q, const float* __restrict__ kv,
    const float* __restrict__ bias, float* __restrict__ o)
{
    __shared__ __align__(16) float qs[NWT * 32];
    __shared__ __align__(16) float ks[NWT * 32];
    __shared__ __align__(16) float vs[NWT * 32];
    __shared__ float ss[NWT * 51];
    const int tid  = threadIdx.x;
    const int win  = blockIdx.x;
    const int head = blockIdx.y;
    const int b  = win >> 6;
    const int w6 = win & 63;
    const int t0 = b * HW + (w6 >> 3) * 7 * HIM + (w6 & 7) * 7;

    for (int idx = tid; idx < NWT * 32; idx += 64) {
        int n = idx >> 5, d = idx & 31;
        int t = t0 + (n / 7) * HIM + (n % 7);
        qs[idx] = q [(size_t)t * CC + head * 32 + d];
        ks[idx] = kv[(size_t)t * (2*CC) + head * 32 + d];
        vs[idx] = kv[(size_t)t * (2*CC) + CC + head * 32 + d];
    }
    __syncthreads();

    const int r = tid;
    if (r < NWT) {
        float4 qr[8];
        #pragma unroll
        for (int i = 0; i < 8; i++) qr[i] = ((const float4*)(qs + r * 32))[i];
        const float* brow = bias + head * (NWT * NWT) + r * NWT;
        float mx = -1e30f;
        for (int c = 0; c < NWT; c++) {
            const float4* kp = (const float4*)(ks + c * 32);
            float acc = 0.f;
            #pragma unroll
            for (int i = 0; i < 8; i++) {
                float4 kk = kp[i];
                acc += qr[i].x * kk.x + qr[i].y * kk.y + qr[i].z * kk.z + qr[i].w * kk.w;
            }
            float s = acc * 0.17677669529663687f + brow[c];
            ss[r * 51 + c] = s;
            mx = fmaxf(mx, s);
        }
        float sum = 0.f;
        for (int c = 0; c < NWT; c++) {
            float e = __expf(ss[r * 51 + c] - mx);
            ss[r * 51 + c] = e;
            sum += e;
        }
        float inv = 1.f / sum;
        float4 oa[8];
        #pragma unroll
        for (int i = 0; i < 8; i++) oa[i] = make_float4(0.f, 0.f, 0.f, 0.f);
        for (int c = 0; c < NWT; c++) {
            float p = ss[r * 51 + c];
            const float4* vp = (const float4*)(vs + c * 32);
            #pragma unroll
            for (int i = 0; i < 8; i++) {
                float4 vv = vp[i];
                oa[i].x += p * vv.x; oa[i].y += p * vv.y;
                oa[i].z += p * vv.z; oa[i].w += p * vv.w;
            }
        }
        int t = t0 + (r / 7) * HIM + (r % 7);
        float4* op = (float4*)(o + (size_t)t * CC + head * 32);
        #pragma unroll
        for (int i = 0; i < 8; i++) {
            oa[i].x *= inv; oa[i].y *= inv; oa[i].z *= inv; oa[i].w *= inv;
            op[i] = oa[i];
        }
    }
}

// ---------------- (B, HW, C) -> (B, C, HW) transpose ----------------
__global__ void transpose_out(const float* __restrict__ in, float* __restrict__ out)
{
    __shared__ float tile[32][33];
    const int b   = blockIdx.z;
    const int hw0 = blockIdx.x * 32;
    const int c0  = blockIdx.y * 32;
    #pragma unroll
    for (int i = 0; i < 4; i++) {
        int r = threadIdx.y + i * 8;
        tile[r][threadIdx.x] = in[((size_t)b * HW + hw0 + r) * CC + c0 + threadIdx.x];
    }
    __syncthreads();
    #pragma unroll
    for (int i = 0; i < 4; i++) {
        int r = threadIdx.y + i * 8;
        out[(size_t)b * CC * HW + (size_t)(c0 + r) * HW + hw0 + threadIdx.x] = tile[threadIdx.x][r];
    }
}

// ---------------- launch ----------------
extern "C" void kernel_launch(void* const* d_in, const int* in_sizes, int n_in,
                              void* d_out, int out_size)
{
    const float* x1      = (const float*)d_in[0];
    const float* x2      = (const float*)d_in[1];
    const float* pe_w    = (const float*)d_in[2];
    const float* pe_b    = (const float*)d_in[3];
    const float* pe_ln_w = (const float*)d_in[4];
    const float* pe_ln_b = (const float*)d_in[5];
    const float* n1_w    = (const float*)d_in[6];
    const float* n1_b    = (const float*)d_in[7];
    const float* q_w     = (const float*)d_in[8];
    const float* q_b     = (const float*)d_in[9];
    const float* kv_w    = (const float*)d_in[10];
    const float* kv_b    = (const float*)d_in[11];
    const float* relb    = (const float*)d_in[12];
    const float* proj_w  = (const float*)d_in[13];
    const float* proj_b  = (const float*)d_in[14];
    const float* n2_w    = (const float*)d_in[15];
    const float* n2_b    = (const float*)d_in[16];
    const float* fc1_w   = (const float*)d_in[17];
    const float* fc1_b   = (const float*)d_in[18];
    const float* fc2_w   = (const float*)d_in[19];
    const float* fc2_b   = (const float*)d_in[20];
    float* out = (float*)d_out;

    float *y, *a, *a2, *qb, *kvb, *ob, *hb, *bb;
    cudaGetSymbolAddress((void**)&y,  g_y);
    cudaGetSymbolAddress((void**)&a,  g_a);
    cudaGetSymbolAddress((void**)&a2, g_a2);
    cudaGetSymbolAddress((void**)&qb, g_q);
    cudaGetSymbolAddress((void**)&kvb,g_kv);
    cudaGetSymbolAddress((void**)&ob, g_o);
    cudaGetSymbolAddress((void**)&hb, g_h);
    cudaGetSymbolAddress((void**)&bb, g_bias);

    // embed x1 -> pre (ob), fused pe_ln + n1 -> y (shortcut), a (attn input)
    gemm_embed_tf32<<<dim3(2, 25, BB), 256>>>(x1, pe_w, pe_b, ob);
    dual_ln<<<TOK, 256>>>(ob, pe_ln_w, pe_ln_b, n1_w, n1_b, y, a);
    // embed x2 -> pre (ob), fused LNs -> a2 only
    gemm_embed_tf32<<<dim3(2, 25, BB), 256>>>(x2, pe_w, pe_b, ob);
    dual_ln<<<TOK, 256>>>(ob, pe_ln_w, pe_ln_b, n1_w, n1_b, nullptr, a2);

    // q / kv projections
    gemm_tf32<0><<<dim3(2, TOK/128), 256>>>(a,  q_w,  q_b,  nullptr, qb,  CC,   CC);
    gemm_tf32<0><<<dim3(4, TOK/128), 256>>>(a2, kv_w, kv_b, nullptr, kvb, 2*CC, CC);

    // relative position bias + attention
    bias_kernel<<<(NHD*NWT*NWT + 255)/256, 256>>>(relb, bb);
    attn_kernel<<<dim3(WINS, NHD), 64>>>(qb, kvb, bb, ob);

    // proj with residual (in-place on y)
    gemm_tf32<1><<<dim3(2, TOK/128), 256>>>(ob, proj_w, proj_b, y, y, CC, CC);

    // MLP: LN -> fc1+GELU -> fc2 + residual
    ln_single<<<TOK, 256>>>(y, n2_w, n2_b, a);
    gemm_tf32<2><<<dim3(8, TOK/128), 256>>>(a,  fc1_w, fc1_b, nullptr, hb, MLPD, CC);
    gemm_tf32<1><<<dim3(2, TOK/128), 256>>>(hb, fc2_w, fc2_b, y, ob, CC, MLPD);

    // (B, HW, C) -> (B, C, H, W)
    transpose_out<<<dim3(HW/32, CC/32, BB), dim3(32, 8)>>>(ob, out);
}

// round 15
// speedup vs baseline: 1.0033x; 1.0019x over previous
#include <cuda_runtime.h>
#include <math.h>

// ---------------- problem constants ----------------
#define BB   16
#define CC   256
#define HIM  56
#define HW   3136            // 56*56
#define TOK  (BB*HW)         // 50176
#define NHD  8               // heads
#define HDD  32              // head dim
#define NWT  49              // tokens per window (7*7)
#define WINS 1024            // B * 64 windows
#define MLPD 1024

// ---------------- scratch (device globals; no cudaMalloc allowed) ----------------
__device__ __align__(256) float g_y [TOK*CC];
__device__ __align__(256) float g_a [TOK*CC];
__device__ __align__(256) float g_a2[TOK*CC];
__device__ __align__(256) float g_q [TOK*CC];
__device__ __align__(256) float g_kv[TOK*2*CC];
__device__ __align__(256) float g_o [TOK*CC];
__device__ __align__(256) float g_h [TOK*MLPD];
__device__ __align__(256) float g_bias[NHD*NWT*NWT];

// ---------------- helpers ----------------
__device__ __forceinline__ unsigned totf32(float x) {
    unsigned r;
    asm("cvt.rna.tf32.f32 %0, %1;" : "=r"(r) : "f"(x));
    return r;
}

__device__ __forceinline__ void mma8(float& c0, float& c1, float& c2, float& c3,
                                     unsigned a0, unsigned a1, unsigned a2, unsigned a3,
                                     unsigned b0, unsigned b1) {
    asm("mma.sync.aligned.m16n8k8.row.col.f32.tf32.tf32.f32 "
        "{%0,%1,%2,%3},{%4,%5,%6,%7},{%8,%9},{%0,%1,%2,%3};"
        : "+f"(c0), "+f"(c1), "+f"(c2), "+f"(c3)
        : "r"(a0), "r"(a1), "r"(a2), "r"(a3), "r"(b0), "r"(b1));
}

// smem column swizzle: conflict-free for both transpose-stores (k varies by 4
// across lanes) and fragment loads (k varies by 1 across lanes).
__device__ __forceinline__ int swz(int k, int m) {
    return m ^ ((((k) & 3) ^ (((k) >> 2) & 3)) << 3);
}

__device__ __forceinline__ float gelu_exact(float x) {
    return 0.5f * x * (1.0f + erff(x * 0.70710678118654752f));
}

__device__ __forceinline__ float2 blockReduce2(float a, float b, float* red) {
    #pragma unroll
    for (int o = 16; o; o >>= 1) {
        a += __shfl_xor_sync(0xffffffffu, a, o);
        b += __shfl_xor_sync(0xffffffffu, b, o);
    }
    __syncthreads();
    int w = threadIdx.x >> 5;
    if ((threadIdx.x & 31) == 0) { red[w] = a; red[8 + w] = b; }
    __syncthreads();
    float ra = 0.f, rb = 0.f;
    #pragma unroll
    for (int i = 0; i < 8; i++) { ra += red[i]; rb += red[8 + i]; }
    return make_float2(ra, rb);
}

// Compute one 128x128x16 tile worth of MMAs from staged smem.
__device__ __forceinline__ void mma_tile(const unsigned (*As)[128], const unsigned (*Bs)[128],
                                         float c[2][8][4], int rowbase, int nbase,
                                         int gr, int gc) {
    #pragma unroll
    for (int ks = 0; ks < 2; ks++) {
        const int k0 = ks * 8;
        unsigned a[2][4];
        #pragma unroll
        for (int mi = 0; mi < 2; mi++) {
            int m0 = rowbase + mi * 16 + gr;
            a[mi][0] = As[k0 + gc    ][swz(k0 + gc,     m0)];
            a[mi][1] = As[k0 + gc    ][swz(k0 + gc,     m0 + 8)];
            a[mi][2] = As[k0 + gc + 4][swz(k0 + gc + 4, m0)];
            a[mi][3] = As[k0 + gc + 4][swz(k0 + gc + 4, m0 + 8)];
        }
        #pragma unroll
        for (int ni = 0; ni < 8; ni++) {
            int n0 = nbase + ni * 8 + gr;
            unsigned b0 = Bs[k0 + gc    ][swz(k0 + gc,     n0)];
            unsigned b1 = Bs[k0 + gc + 4][swz(k0 + gc + 4, n0)];
            mma8(c[0][ni][0], c[0][ni][1], c[0][ni][2], c[0][ni][3],
                 a[0][0], a[0][1], a[0][2], a[0][3], b0, b1);
            mma8(c[1][ni][0], c[1][ni][1], c[1][ni][2], c[1][ni][3],
                 a[1][0], a[1][1], a[1][2], a[1][3], b0, b1);
        }
    }
}

// ---------------- tf32 tensor-core GEMM: C[m,n] = A[m,:]·W[n,:] + bias[n] ----------------
// A row-major M x K, W row-major N x K. M,N multiples of 128, K multiple of 16.
// EPI: 0 = bias, 1 = bias + residual R, 2 = bias + exact GELU.
template<int EPI>
__global__ __launch_bounds__(256, 2) void gemm_tf32(
    const float* __restrict__ A, const float* __restrict__ W,
    const float* __restrict__ bias, const float* __restrict__ R,
    float* __restrict__ C, int Nn, int K)
{
    __shared__ __align__(16) unsigned As[16][128];
    __shared__ __align__(16) unsigned Bs[16][128];
    const int tid = threadIdx.x;
    const int nt = blockIdx.x * 128;
    const int mt = blockIdx.y * 128;
    const int lr = tid >> 2;           // 0..63
    const int lk = (tid & 3) * 4;      // 0,4,8,12
    const float* Ap0 = A + (size_t)(mt + lr)      * K + lk;
    const float* Ap1 = A + (size_t)(mt + lr + 64) * K + lk;
    const float* Wp0 = W + (size_t)(nt + lr)      * K + lk;
    const float* Wp1 = W + (size_t)(nt + lr + 64) * K + lk;

    const int lane = tid & 31;
    const int wid  = tid >> 5;
    const int gr = lane >> 2, gc = lane & 3;
    const int rowbase = (wid & 3) * 32;
    const int nbase   = (wid >> 2) * 64;

    float c[2][8][4];
    #pragma unroll
    for (int mi = 0; mi < 2; mi++)
        #pragma unroll
        for (int ni = 0; ni < 8; ni++)
            #pragma unroll
            for (int j = 0; j < 4; j++) c[mi][ni][j] = 0.f;

    float4 a0v = *(const float4*)Ap0;
    float4 a1v = *(const float4*)Ap1;
    float4 b0v = *(const float4*)Wp0;
    float4 b1v = *(const float4*)Wp1;

    for (int kt = 0; kt < K; kt += 16) {
        {
            float av0[4] = {a0v.x, a0v.y, a0v.z, a0v.w};
            float av1[4] = {a1v.x, a1v.y, a1v.z, a1v.w};
            float bv0[4] = {b0v.x, b0v.y, b0v.z, b0v.w};
            float bv1[4] = {b1v.x, b1v.y, b1v.z, b1v.w};
            #pragma unroll
            for (int i = 0; i < 4; i++) {
                As[lk + i][swz(lk + i, lr)]      = totf32(av0[i]);
                As[lk + i][swz(lk + i, lr + 64)] = totf32(av1[i]);
                Bs[lk + i][swz(lk + i, lr)]      = totf32(bv0[i]);
                Bs[lk + i][swz(lk + i, lr + 64)] = totf32(bv1[i]);
            }
        }
        __syncthreads();
        if (kt + 16 < K) {
            a0v = *(const float4*)(Ap0 + kt + 16);
            a1v = *(const float4*)(Ap1 + kt + 16);
            b0v = *(const float4*)(Wp0 + kt + 16);
            b1v = *(const float4*)(Wp1 + kt + 16);
        }
        mma_tile(As, Bs, c, rowbase, nbase, gr, gc);
        __syncthreads();
    }

    // epilogue: fragment (row, col) mapping for m16n8 f32 accumulators
    #pragma unroll
    for (int ni = 0; ni < 8; ni++) {
        int col = nt + nbase + ni * 8 + gc * 2;
        float2 bv = *(const float2*)(bias + col);
        #pragma unroll
        for (int mi = 0; mi < 2; mi++) {
            int r0 = mt + rowbase + mi * 16 + gr;
            float2 v0 = make_float2(c[mi][ni][0] + bv.x, c[mi][ni][1] + bv.y);
            float2 v1 = make_float2(c[mi][ni][2] + bv.x, c[mi][ni][3] + bv.y);
            size_t o0 = (size_t)r0 * Nn + col;
            size_t o1 = (size_t)(r0 + 8) * Nn + col;
            if (EPI == 1) {
                float2 r0v = *(const float2*)(R + o0);
                float2 r1v = *(const float2*)(R + o1);
                v0.x += r0v.x; v0.y += r0v.y;
                v1.x += r1v.x; v1.y += r1v.y;
            }
            if (EPI == 2) {
                v0.x = gelu_exact(v0.x); v0.y = gelu_exact(v0.y);
                v1.x = gelu_exact(v1.x); v1.y = gelu_exact(v1.y);
            }
            *(float2*)(C + o0) = v0;
            *(float2*)(C + o1) = v1;
        }
    }
}

// ---------------- embed GEMM (tf32): y[b*HW+m, n] = sum_k x[b,k,m]*pe_w[n,k] + pe_b[n] ----------
__global__ __launch_bounds__(256, 2) void gemm_embed_tf32(
    const float* __restrict__ X, const float* __restrict__ W,
    const float* __restrict__ bias, float* __restrict__ C)
{
    __shared__ __align__(16) unsigned As[16][128];
    __shared__ __align__(16) unsigned Bs[16][128];
    const int tid = threadIdx.x;
    const int nt = blockIdx.x * 128;
    const int mt = blockIdx.y * 128;
    const int b  = blockIdx.z;
    const float* A = X + (size_t)b * CC * HW;

    const int lkE = tid >> 4;          // 0..15
    const int lmE = (tid & 15) * 8;    // 0..120
    const bool mok = (mt + lmE) < HW;  // 8-runs entirely in/out (HW%8==0)
    const float* ApE = A + (size_t)lkE * HW + mt + lmE;
    const int xorA = (((lkE & 3) ^ ((lkE >> 2) & 3)) << 3);
    unsigned* dstA = &As[lkE][lmE ^ xorA];

    const int lr = tid >> 2;
    const int lk = (tid & 3) * 4;
    const float* Wp0 = W + (size_t)(nt + lr)      * CC + lk;
    const float* Wp1 = W + (size_t)(nt + lr + 64) * CC + lk;

    const int lane = tid & 31;
    const int wid  = tid >> 5;
    const int gr = lane >> 2, gc = lane & 3;
    const int rowbase = (wid & 3) * 32;
    const int nbase   = (wid >> 2) * 64;

    float c[2][8][4];
    #pragma unroll
    for (int mi = 0; mi < 2; mi++)
        #pragma unroll
        for (int ni = 0; ni < 8; ni++)
            #pragma unroll
            for (int j = 0; j < 4; j++) c[mi][ni][j] = 0.f;

    const float4 z4 = make_float4(0.f, 0.f, 0.f, 0.f);
    float4 a0v = mok ? *(const float4*)(ApE)     : z4;
    float4 a1v = mok ? *(const float4*)(ApE + 4) : z4;
    float4 b0v = *(const float4*)Wp0;
    float4 b1v = *(const float4*)Wp1;

    for (int kt = 0; kt < CC; kt += 16) {
        {
            uint4 u0 = make_uint4(totf32(a0v.x), totf32(a0v.y), totf32(a0v.z), totf32(a0v.w));
            uint4 u1 = make_uint4(totf32(a1v.x), totf32(a1v.y), totf32(a1v.z), totf32(a1v.w));
            *(uint4*)dstA       = u0;
            *(uint4*)(dstA + 4) = u1;
            float bv0[4] = {b0v.x, b0v.y, b0v.z, b0v.w};
            float bv1[4] = {b1v.x, b1v.y, b1v.z, b1v.w};
            #pragma unroll
            for (int i = 0; i < 4; i++) {
                Bs[lk + i][swz(lk + i, lr)]      = totf32(bv0[i]);
                Bs[lk + i][swz(lk + i, lr + 64)] = totf32(bv1[i]);
            }
        }
        __syncthreads();
        if (kt + 16 < CC) {
            a0v = mok ? *(const float4*)(ApE + (size_t)(kt + 16) * HW)     : z4;
            a1v = mok ? *(const float4*)(ApE + (size_t)(kt + 16) * HW + 4) : z4;
            b0v = *(const float4*)(Wp0 + kt + 16);
            b1v = *(const float4*)(Wp1 + kt + 16);
        }
        mma_tile(As, Bs, c, rowbase, nbase, gr, gc);
        __syncthreads();
    }

    #pragma unroll
    for (int ni = 0; ni < 8; ni++) {
        int col = nt + nbase + ni * 8 + gc * 2;
        float2 bv = *(const float2*)(bias + col);
        #pragma unroll
        for (int mi = 0; mi < 2; mi++) {
            int mr0 = mt + rowbase + mi * 16 + gr;
            if (mr0 < HW) {
                float2 v0 = make_float2(c[mi][ni][0] + bv.x, c[mi][ni][1] + bv.y);
                *(float2*)(C + ((size_t)b * HW + mr0) * CC + col) = v0;
            }
            if (mr0 + 8 < HW) {
                float2 v1 = make_float2(c[mi][ni][2] + bv.x, c[mi][ni][3] + bv.y);
                *(float2*)(C + ((size_t)b * HW + mr0 + 8) * CC + col) = v1;
            }
        }
    }
}

// ---------------- fused double LayerNorm (pe_ln then n1) ----------------
__global__ __launch_bounds__(256) void dual_ln(
    const float* __restrict__ in,
    const float* __restrict__ w1, const float* __restrict__ b1,
    const float* __restrict__ w2, const float* __restrict__ b2,
    float* __restrict__ yOut, float* __restrict__ aOut)
{
    __shared__ float red[16];
    const size_t t = blockIdx.x;
    const int c = threadIdx.x;
    float v = in[t * CC + c];
    float2 s = blockReduce2(v, v * v, red);
    float mean = s.x * (1.f / CC);
    float var  = s.y * (1.f / CC) - mean * mean;
    float y = (v - mean) * rsqrtf(var + 1e-5f) * w1[c] + b1[c];
    if (yOut) yOut[t * CC + c] = y;
    float2 s2 = blockReduce2(y, y * y, red);
    float mean2 = s2.x * (1.f / CC);
    float var2  = s2.y * (1.f / CC) - mean2 * mean2;
    aOut[t * CC + c] = (y - mean2) * rsqrtf(var2 + 1e-5f) * w2[c] + b2[c];
}

__global__ __launch_bounds__(256) void ln_single(
    const float* __restrict__ in,
    const float* __restrict__ w, const float* __restrict__ b,
    float* __restrict__ outp)
{
    __shared__ float red[16];
    const size_t t = blockIdx.x;
    const int c = threadIdx.x;
    float v = in[t * CC + c];
    float2 s = blockReduce2(v, v * v, red);
    float mean = s.x * (1.f / CC);
    float var  = s.y * (1.f / CC) - mean * mean;
    outp[t * CC + c] = (v - mean) * rsqrtf(var + 1e-5f) * w[c] + b[c];
}

// ---------------- relative position bias expand: (NH, 49, 49) ----------------
__global__ void bias_kernel(const float* __restrict__ rel, float* __restrict__ bout)
{
    int idx = blockIdx.x * blockDim.x + threadIdx.x;
    if (idx >= NHD * NWT * NWT) return;
    int h  = idx / (NWT * NWT);
    int pq = idx % (NWT * NWT);
    int p = pq / NWT, q = pq % NWT;
    int i1 = p / 7, j1 = p % 7, i2 = q / 7, j2 = q % 7;
    int ridx = (i1 - i2 + 6) * 13 + (j1 - j2 + 6);
    bout[idx] = rel[ridx * NHD + h];
}

// ---------------- windowed attention: per (window, head) ----------------
__global__ __launch_bounds__(64) void attn_kernel(
    const float* __restrict__ q, const float* __restrict__ kv,
    const float* __restrict__ bias, float* __restrict__ o)
{
    __shared__ __align__(16) float qs[NWT * 32];
    __shared__ __align__(16) float ks[NWT * 32];
    __shared__ __align__(16) float vs[NWT * 32];
    __shared__ float ss[NWT * 51];
    const int tid  = threadIdx.x;
    const int win  = blockIdx.x;
    const int head = blockIdx.y;
    const int b  = win >> 6;
    const int w6 = win & 63;
    const int t0 = b * HW + (w6 >> 3) * 7 * HIM + (w6 & 7) * 7;

    for (int idx = tid; idx < NWT * 32; idx += 64) {
        int n = idx >> 5, d = idx & 31;
        int t = t0 + (n / 7) * HIM + (n % 7);
        qs[idx] = q [(size_t)t * CC + head * 32 + d];
        ks[idx] = kv[(size_t)t * (2*CC) + head * 32 + d];
        vs[idx] = kv[(size_t)t * (2*CC) + CC + head * 32 + d];
    }
    __syncthreads();

    const int r = tid;
    if (r < NWT) {
        float4 qr[8];
        #pragma unroll
        for (int i = 0; i < 8; i++) qr[i] = ((const float4*)(qs + r * 32))[i];
        const float* brow = bias + head * (NWT * NWT) + r * NWT;
        float mx = -1e30f;
        for (int c = 0; c < NWT; c++) {
            const float4* kp = (const float4*)(ks + c * 32);
            float acc = 0.f;
            #pragma unroll
            for (int i = 0; i < 8; i++) {
                float4 kk = kp[i];
                acc += qr[i].x * kk.x + qr[i].y * kk.y + qr[i].z * kk.z + qr[i].w * kk.w;
            }
            float s = acc * 0.17677669529663687f + brow[c];
            ss[r * 51 + c] = s;
            mx = fmaxf(mx, s);
        }
        float sum = 0.f;
        for (int c = 0; c < NWT; c++) {
            float e = __expf(ss[r * 51 + c] - mx);
            ss[r * 51 + c] = e;
            sum += e;
        }
        float inv = 1.f / sum;
        float4 oa[8];
        #pragma unroll
        for (int i = 0; i < 8; i++) oa[i] = make_float4(0.f, 0.f, 0.f, 0.f);
        for (int c = 0; c < NWT; c++) {
            float p = ss[r * 51 + c];
            const float4* vp = (const float4*)(vs + c * 32);
            #pragma unroll
            for (int i = 0; i < 8; i++) {
                float4 vv = vp[i];
                oa[i].x += p * vv.x; oa[i].y += p * vv.y;
                oa[i].z += p * vv.z; oa[i].w += p * vv.w;
            }
        }
        int t = t0 + (r / 7) * HIM + (r % 7);
        float4* op = (float4*)(o + (size_t)t * CC + head * 32);
        #pragma unroll
        for (int i = 0; i < 8; i++) {
            oa[i].x *= inv; oa[i].y *= inv; oa[i].z *= inv; oa[i].w *= inv;
            op[i] = oa[i];
        }
    }
}

// ---------------- (B, HW, C) -> (B, C, HW) transpose ----------------
__global__ void transpose_out(const float* __restrict__ in, float* __restrict__ out)
{
    __shared__ float tile[32][33];
    const int b   = blockIdx.z;
    const int hw0 = blockIdx.x * 32;
    const int c0  = blockIdx.y * 32;
    #pragma unroll
    for (int i = 0; i < 4; i++) {
        int r = threadIdx.y + i * 8;
        tile[r][threadIdx.x] = in[((size_t)b * HW + hw0 + r) * CC + c0 + threadIdx.x];
    }
    __syncthreads();
    #pragma unroll
    for (int i = 0; i < 4; i++) {
        int r = threadIdx.y + i * 8;
        out[(size_t)b * CC * HW + (size_t)(c0 + r) * HW + hw0 + threadIdx.x] = tile[threadIdx.x][r];
    }
}

// ---------------- launch ----------------
extern "C" void kernel_launch(void* const* d_in, const int* in_sizes, int n_in,
                              void* d_out, int out_size)
{
    const float* x1      = (const float*)d_in[0];
    const float* x2      = (const float*)d_in[1];
    const float* pe_w    = (const float*)d_in[2];
    const float* pe_b    = (const float*)d_in[3];
    const float* pe_ln_w = (const float*)d_in[4];
    const float* pe_ln_b = (const float*)d_in[5];
    const float* n1_w    = (const float*)d_in[6];
    const float* n1_b    = (const float*)d_in[7];
    const float* q_w     = (const float*)d_in[8];
    const float* q_b     = (const float*)d_in[9];
    const float* kv_w    = (const float*)d_in[10];
    const float* kv_b    = (const float*)d_in[11];
    const float* relb    = (const float*)d_in[12];
    const float* proj_w  = (const float*)d_in[13];
    const float* proj_b  = (const float*)d_in[14];
    const float* n2_w    = (const float*)d_in[15];
    const float* n2_b    = (const float*)d_in[16];
    const float* fc1_w   = (const float*)d_in[17];
    const float* fc1_b   = (const float*)d_in[18];
    const float* fc2_w   = (const float*)d_in[19];
    const float* fc2_b   = (const float*)d_in[20];
    float* out = (float*)d_out;

    float *y, *a, *a2, *qb, *kvb, *ob, *hb, *bb;
    cudaGetSymbolAddress((void**)&y,  g_y);
    cudaGetSymbolAddress((void**)&a,  g_a);
    cudaGetSymbolAddress((void**)&a2, g_a2);
    cudaGetSymbolAddress((void**)&qb, g_q);
    cudaGetSymbolAddress((void**)&kvb,g_kv);
    cudaGetSymbolAddress((void**)&ob, g_o);
    cudaGetSymbolAddress((void**)&hb, g_h);
    cudaGetSymbolAddress((void**)&bb, g_bias);

    // embed x1 -> pre (ob), fused pe_ln + n1 -> y (shortcut), a (attn input)
    gemm_embed_tf32<<<dim3(2, 25, BB), 256>>>(x1, pe_w, pe_b, ob);
    dual_ln<<<TOK, 256>>>(ob, pe_ln_w, pe_ln_b, n1_w, n1_b, y, a);
    // embed x2 -> pre (ob), fused LNs -> a2 only
    gemm_embed_tf32<<<dim3(2, 25, BB), 256>>>(x2, pe_w, pe_b, ob);
    dual_ln<<<TOK, 256>>>(ob, pe_ln_w, pe_ln_b, n1_w, n1_b, nullptr, a2);

    // q / kv projections
    gemm_tf32<0><<<dim3(2, TOK/128), 256>>>(a,  q_w,  q_b,  nullptr, qb,  CC,   CC);
    gemm_tf32<0><<<dim3(4, TOK/128), 256>>>(a2, kv_w, kv_b, nullptr, kvb, 2*CC, CC);

    // relative position bias + attention
    bias_kernel<<<(NHD*NWT*NWT + 255)/256, 256>>>(relb, bb);
    attn_kernel<<<dim3(WINS, NHD), 64>>>(qb, kvb, bb, ob);

    // proj with residual (in-place on y)
    gemm_tf32<1><<<dim3(2, TOK/128), 256>>>(ob, proj_w, proj_b, y, y, CC, CC);

    // MLP: LN -> fc1+GELU -> fc2 + residual
    ln_single<<<TOK, 256>>>(y, n2_w, n2_b, a);
    gemm_tf32<2><<<dim3(8, TOK/128), 256>>>(a,  fc1_w, fc1_b, nullptr, hb, MLPD, CC);
    gemm_tf32<1><<<dim3(2, TOK/128), 256>>>(hb, fc2_w, fc2_b, y, ob, CC, MLPD);

    // (B, HW, C) -> (B, C, H, W)
    transpose_out<<<dim3(HW/32, CC/32, BB), dim3(32, 8)>>>(ob, out);
}

// round 17
// speedup vs baseline: 2.4289x; 2.4209x over previous
#include <cuda_runtime.h>
#include <cuda_fp16.h>
#include <math.h>
#include <stdint.h>

// ---------------- problem constants ----------------
#define BB   16
#define CC   256
#define HIM  56
#define HW   3136            // 56*56
#define TOK  (BB*HW)         // 50176
#define NHD  8
#define NWT  49
#define WINS 1024
#define MLPD 1024

// ---------------- scratch (device globals; no cudaMalloc allowed) ----------------
__device__ __align__(256) float g_y [TOK*CC];
__device__ __align__(256) float g_a [TOK*CC];
__device__ __align__(256) float g_a2[TOK*CC];
__device__ __align__(256) float g_q [TOK*CC];
__device__ __align__(256) float g_kv[TOK*2*CC];
__device__ __align__(256) float g_o [TOK*CC];
__device__ __align__(256) float g_h [TOK*MLPD];   // fc1 out; also transposed x1/x2 staging
__device__ __align__(256) float g_bias[NHD*NWT*NWT];

// ---------------- helpers ----------------
__device__ __forceinline__ float gelu_exact(float x) {
    return 0.5f * x * (1.0f + erff(x * 0.70710678118654752f));
}

__device__ __forceinline__ float2 blockReduce2(float a, float b, float* red) {
    #pragma unroll
    for (int o = 16; o; o >>= 1) {
        a += __shfl_xor_sync(0xffffffffu, a, o);
        b += __shfl_xor_sync(0xffffffffu, b, o);
    }
    __syncthreads();
    int w = threadIdx.x >> 5;
    if ((threadIdx.x & 31) == 0) { red[w] = a; red[8 + w] = b; }
    __syncthreads();
    float ra = 0.f, rb = 0.f;
    #pragma unroll
    for (int i = 0; i < 8; i++) { ra += red[i]; rb += red[8 + i]; }
    return make_float2(ra, rb);
}

__device__ __forceinline__ void ldsm4(uint32_t (&r)[4], uint32_t addr) {
    asm volatile("ldmatrix.sync.aligned.m8n8.x4.shared.b16 {%0,%1,%2,%3}, [%4];"
        : "=r"(r[0]), "=r"(r[1]), "=r"(r[2]), "=r"(r[3]) : "r"(addr));
}

__device__ __forceinline__ void mma16816(float (&c)[4], const uint32_t (&a)[4],
                                         uint32_t b0, uint32_t b1) {
    asm volatile("mma.sync.aligned.m16n8k16.row.col.f32.f16.f16.f32 "
        "{%0,%1,%2,%3},{%4,%5,%6,%7},{%8,%9},{%0,%1,%2,%3};"
        : "+f"(c[0]), "+f"(c[1]), "+f"(c[2]), "+f"(c[3])
        : "r"(a[0]), "r"(a[1]), "r"(a[2]), "r"(a[3]), "r"(b0), "r"(b1));
}

// smem tile: 128 rows x 32 halfs (64B/row). 16B-column swizzle: c16 ^= (row>>1)&3.
// Verified conflict-free for ldmatrix (8 lanes -> 8 distinct 16B groups per phase).
__device__ __forceinline__ uint32_t swz_off(int row, int c16) {
    return (uint32_t)row * 64u + (uint32_t)((c16 ^ ((row >> 1) & 3)) << 4);
}

// ---------------- fp16 tensor-core GEMM: C[m,n] = A[m,:]·W[n,:] + bias[n] (+EPI) ------
// A row-major M x K (fp32), W row-major N x K (fp32). M,N multiples of 128, K of 32.
// EPI: 0 = bias, 1 = bias + residual R, 2 = bias + exact GELU.
template<int EPI>
__global__ __launch_bounds__(256) void gemm_h(
    const float* __restrict__ A, const float* __restrict__ W,
    const float* __restrict__ bias, const float* __restrict__ R,
    float* __restrict__ C, int Nn, int K)
{
    __shared__ __align__(16) __half As[128 * 32];
    __shared__ __align__(16) __half Bs[128 * 32];

    const int tid  = threadIdx.x;
    const int lane = tid & 31;
    const int wid  = tid >> 5;
    const int wm   = wid & 3;          // 4 m-warps: 32 rows each
    const int wn   = wid >> 2;         // 2 n-warps: 64 cols each
    const int nt = blockIdx.x * 128;
    const int mt = blockIdx.y * 128;

    // staging: thread t -> rows r0+32p (p=0..3), halfs [hb*4, hb*4+4)
    const int r0 = tid >> 3;
    const int hb = tid & 7;
    const int c16s = hb >> 1;
    const int b8   = (hb & 1) * 8;
    const float* Ald = A + (size_t)(mt + r0) * K + hb * 4;
    const float* Wld = W + (size_t)(nt + r0) * K + hb * 4;

    char* dstA[4];
    char* dstB[4];
    #pragma unroll
    for (int p = 0; p < 4; p++) {
        int r = r0 + 32 * p;
        uint32_t off = swz_off(r, c16s) + b8;
        dstA[p] = (char*)As + off;
        dstB[p] = (char*)Bs + off;
    }

    const uint32_t AsA = (uint32_t)__cvta_generic_to_shared(As);
    const uint32_t BsA = (uint32_t)__cvta_generic_to_shared(Bs);
    const int j = lane & 7, quad = lane >> 3;

    float acc[2][8][4];
    #pragma unroll
    for (int mb = 0; mb < 2; mb++)
        #pragma unroll
        for (int nb = 0; nb < 8; nb++)
            #pragma unroll
            for (int i = 0; i < 4; i++) acc[mb][nb][i] = 0.f;

    float4 pa[4], pb[4];
    #pragma unroll
    for (int p = 0; p < 4; p++) {
        pa[p] = *(const float4*)(Ald + (size_t)(32 * p) * K);
        pb[p] = *(const float4*)(Wld + (size_t)(32 * p) * K);
    }

    // ldmatrix per-lane row/col pieces
    const int rowA = wm * 32 + (quad & 1) * 8 + j;     // + mb*16
    const int dkA  = quad >> 1;                        // c16 += ks*2
    const int rowB = wn * 64 + (quad >> 1) * 8 + j;    // + nbp*16
    const int dkB  = quad & 1;

    for (int kt = 0; kt < K; kt += 32) {
        #pragma unroll
        for (int p = 0; p < 4; p++) {
            half2 h0 = __floats2half2_rn(pa[p].x, pa[p].y);
            half2 h1 = __floats2half2_rn(pa[p].z, pa[p].w);
            uint2 u;
            u.x = *reinterpret_cast<uint32_t*>(&h0);
            u.y = *reinterpret_cast<uint32_t*>(&h1);
            *(uint2*)dstA[p] = u;
            h0 = __floats2half2_rn(pb[p].x, pb[p].y);
            h1 = __floats2half2_rn(pb[p].z, pb[p].w);
            u.x = *reinterpret_cast<uint32_t*>(&h0);
            u.y = *reinterpret_cast<uint32_t*>(&h1);
            *(uint2*)dstB[p] = u;
        }
        __syncthreads();
        if (kt + 32 < K) {
            #pragma unroll
            for (int p = 0; p < 4; p++) {
                pa[p] = *(const float4*)(Ald + (size_t)(32 * p) * K + kt + 32);
                pb[p] = *(const float4*)(Wld + (size_t)(32 * p) * K + kt + 32);
            }
        }
        #pragma unroll
        for (int ks = 0; ks < 2; ks++) {
            uint32_t a[2][4];
            #pragma unroll
            for (int mb = 0; mb < 2; mb++) {
                int row = rowA + mb * 16;
                ldsm4(a[mb], AsA + swz_off(row, ks * 2 + dkA));
            }
            #pragma unroll
            for (int nbp = 0; nbp < 4; nbp++) {
                int row = rowB + nbp * 16;
                uint32_t b[4];
                ldsm4(b, BsA + swz_off(row, ks * 2 + dkB));
                mma16816(acc[0][2*nbp],     a[0], b[0], b[1]);
                mma16816(acc[1][2*nbp],     a[1], b[0], b[1]);
                mma16816(acc[0][2*nbp + 1], a[0], b[2], b[3]);
                mma16816(acc[1][2*nbp + 1], a[1], b[2], b[3]);
            }
        }
        __syncthreads();
    }

    // epilogue: c0,c1 -> (row, col..col+1); c2,c3 -> (row+8, same cols)
    const int grow = lane >> 2, gc = lane & 3;
    #pragma unroll
    for (int nb = 0; nb < 8; nb++) {
        int col = nt + wn * 64 + nb * 8 + gc * 2;
        float2 bv = *(const float2*)(bias + col);
        #pragma unroll
        for (int mb = 0; mb < 2; mb++) {
            int row = mt + wm * 32 + mb * 16 + grow;
            size_t o0 = (size_t)row * Nn + col;
            size_t o1 = o0 + (size_t)8 * Nn;
            float2 v0 = make_float2(acc[mb][nb][0] + bv.x, acc[mb][nb][1] + bv.y);
            float2 v1 = make_float2(acc[mb][nb][2] + bv.x, acc[mb][nb][3] + bv.y);
            if (EPI == 1) {
                float2 r0v = *(const float2*)(R + o0);
                float2 r1v = *(const float2*)(R + o1);
                v0.x += r0v.x; v0.y += r0v.y;
                v1.x += r1v.x; v1.y += r1v.y;
            }
            if (EPI == 2) {
                v0.x = gelu_exact(v0.x); v0.y = gelu_exact(v0.y);
                v1.x = gelu_exact(v1.x); v1.y = gelu_exact(v1.y);
            }
            *(float2*)(C + o0) = v0;
            *(float2*)(C + o1) = v1;
        }
    }
}

// ---------------- (B, C, HW) -> (B, HW, C) transpose (embed input) ----------------
__global__ void transpose_in(const float* __restrict__ in, float* __restrict__ out)
{
    __shared__ float tile[32][33];
    const int b  = blockIdx.z;
    const int m0 = blockIdx.x * 32;   // HW
    const int c0 = blockIdx.y * 32;   // C
    #pragma unroll
    for (int i = 0; i < 4; i++) {
        int r = threadIdx.y + i * 8;
        tile[r][threadIdx.x] = in[(size_t)b * CC * HW + (size_t)(c0 + r) * HW + m0 + threadIdx.x];
    }
    __syncthreads();
    #pragma unroll
    for (int i = 0; i < 4; i++) {
        int r = threadIdx.y + i * 8;
        out[((size_t)b * HW + m0 + r) * CC + c0 + threadIdx.x] = tile[threadIdx.x][r];
    }
}

// ---------------- fused double LayerNorm (pe_ln then n1) ----------------
__global__ __launch_bounds__(256) void dual_ln(
    const float* __restrict__ in,
    const float* __restrict__ w1, const float* __restrict__ b1,
    const float* __restrict__ w2, const float* __restrict__ b2,
    float* __restrict__ yOut, float* __restrict__ aOut)
{
    __shared__ float red[16];
    const size_t t = blockIdx.x;
    const int c = threadIdx.x;
    float v = in[t * CC + c];
    float2 s = blockReduce2(v, v * v, red);
    float mean = s.x * (1.f / CC);
    float var  = s.y * (1.f / CC) - mean * mean;
    float y = (v - mean) * rsqrtf(var + 1e-5f) * w1[c] + b1[c];
    if (yOut) yOut[t * CC + c] = y;
    float2 s2 = blockReduce2(y, y * y, red);
    float mean2 = s2.x * (1.f / CC);
    float var2  = s2.y * (1.f / CC) - mean2 * mean2;
    aOut[t * CC + c] = (y - mean2) * rsqrtf(var2 + 1e-5f) * w2[c] + b2[c];
}

__global__ __launch_bounds__(256) void ln_single(
    const float* __restrict__ in,
    const float* __restrict__ w, const float* __restrict__ b,
    float* __restrict__ outp)
{
    __shared__ float red[16];
    const size_t t = blockIdx.x;
    const int c = threadIdx.x;
    float v = in[t * CC + c];
    float2 s = blockReduce2(v, v * v, red);
    float mean = s.x * (1.f / CC);
    float var  = s.y * (1.f / CC) - mean * mean;
    outp[t * CC + c] = (v - mean) * rsqrtf(var + 1e-5f) * w[c] + b[c];
}

// ---------------- relative position bias expand: (NH, 49, 49) ----------------
__global__ void bias_kernel(const float* __restrict__ rel, float* __restrict__ bout)
{
    int idx = blockIdx.x * blockDim.x + threadIdx.x;
    if (idx >= NHD * NWT * NWT) return;
    int h  = idx / (NWT * NWT);
    int pq = idx % (NWT * NWT);
    int p = pq / NWT, q = pq % NWT;
    int i1 = p / 7, j1 = p % 7, i2 = q / 7, j2 = q % 7;
    int ridx = (i1 - i2 + 6) * 13 + (j1 - j2 + 6);
    bout[idx] = rel[ridx * NHD + h];
}

// ---------------- windowed attention: per (window, head) ----------------
__global__ __launch_bounds__(64) void attn_kernel(
    const float* __restrict__ q, const float* __restrict__ kv,
    const float* __restrict__ bias, float* __restrict__ o)
{
    __shared__ __align__(16) float qs[NWT * 32];
    __shared__ __align__(16) float ks[NWT * 32];
    __shared__ __align__(16) float vs[NWT * 32];
    __shared__ float ss[NWT * 51];
    const int tid  = threadIdx.x;
    const int win  = blockIdx.x;
    const int head = blockIdx.y;
    const int b  = win >> 6;
    const int w6 = win & 63;
    const int t0 = b * HW + (w6 >> 3) * 7 * HIM + (w6 & 7) * 7;

    for (int idx = tid; idx < NWT * 32; idx += 64) {
        int n = idx >> 5, d = idx & 31;
        int t = t0 + (n / 7) * HIM + (n % 7);
        qs[idx] = q [(size_t)t * CC + head * 32 + d];
        ks[idx] = kv[(size_t)t * (2*CC) + head * 32 + d];
        vs[idx] = kv[(size_t)t * (2*CC) + CC + head * 32 + d];
    }
    __syncthreads();

    const int r = tid;
    if (r < NWT) {
        float4 qr[8];
        #pragma unroll
        for (int i = 0; i < 8; i++) qr[i] = ((const float4*)(qs + r * 32))[i];
        const float* brow = bias + head * (NWT * NWT) + r * NWT;
        float mx = -1e30f;
        for (int c = 0; c < NWT; c++) {
            const float4* kp = (const float4*)(ks + c * 32);
            float acc = 0.f;
            #pragma unroll
            for (int i = 0; i < 8; i++) {
                float4 kk = kp[i];
                acc += qr[i].x * kk.x + qr[i].y * kk.y + qr[i].z * kk.z + qr[i].w * kk.w;
            }
            float s = acc * 0.17677669529663687f + brow[c];
            ss[r * 51 + c] = s;
            mx = fmaxf(mx, s);
        }
        float sum = 0.f;
        for (int c = 0; c < NWT; c++) {
            float e = __expf(ss[r * 51 + c] - mx);
            ss[r * 51 + c] = e;
            sum += e;
        }
        float inv = 1.f / sum;
        float4 oa[8];
        #pragma unroll
        for (int i = 0; i < 8; i++) oa[i] = make_float4(0.f, 0.f, 0.f, 0.f);
        for (int c = 0; c < NWT; c++) {
            float p = ss[r * 51 + c];
            const float4* vp = (const float4*)(vs + c * 32);
            #pragma unroll
            for (int i = 0; i < 8; i++) {
                float4 vv = vp[i];
                oa[i].x += p * vv.x; oa[i].y += p * vv.y;
                oa[i].z += p * vv.z; oa[i].w += p * vv.w;
            }
        }
        int t = t0 + (r / 7) * HIM + (r % 7);
        float4* op = (float4*)(o + (size_t)t * CC + head * 32);
        #pragma unroll
        for (int i = 0; i < 8; i++) {
            oa[i].x *= inv; oa[i].y *= inv; oa[i].z *= inv; oa[i].w *= inv;
            op[i] = oa[i];
        }
    }
}

// ---------------- (B, HW, C) -> (B, C, HW) transpose ----------------
__global__ void transpose_out(const float* __restrict__ in, float* __restrict__ out)
{
    __shared__ float tile[32][33];
    const int b   = blockIdx.z;
    const int hw0 = blockIdx.x * 32;
    const int c0  = blockIdx.y * 32;
    #pragma unroll
    for (int i = 0; i < 4; i++) {
        int r = threadIdx.y + i * 8;
        tile[r][threadIdx.x] = in[((size_t)b * HW + hw0 + r) * CC + c0 + threadIdx.x];
    }
    __syncthreads();
    #pragma unroll
    for (int i = 0; i < 4; i++) {
        int r = threadIdx.y + i * 8;
        out[(size_t)b * CC * HW + (size_t)(c0 + r) * HW + hw0 + threadIdx.x] = tile[threadIdx.x][r];
    }
}

// ---------------- launch ----------------
extern "C" void kernel_launch(void* const* d_in, const int* in_sizes, int n_in,
                              void* d_out, int out_size)
{
    const float* x1      = (const float*)d_in[0];
    const float* x2      = (const float*)d_in[1];
    const float* pe_w    = (const float*)d_in[2];
    const float* pe_b    = (const float*)d_in[3];
    const float* pe_ln_w = (const float*)d_in[4];
    const float* pe_ln_b = (const float*)d_in[5];
    const float* n1_w    = (const float*)d_in[6];
    const float* n1_b    = (const float*)d_in[7];
    const float* q_w     = (const float*)d_in[8];
    const float* q_b     = (const float*)d_in[9];
    const float* kv_w    = (const float*)d_in[10];
    const float* kv_b    = (const float*)d_in[11];
    const float* relb    = (const float*)d_in[12];
    const float* proj_w  = (const float*)d_in[13];
    const float* proj_b  = (const float*)d_in[14];
    const float* n2_w    = (const float*)d_in[15];
    const float* n2_b    = (const float*)d_in[16];
    const float* fc1_w   = (const float*)d_in[17];
    const float* fc1_b   = (const float*)d_in[18];
    const float* fc2_w   = (const float*)d_in[19];
    const float* fc2_b   = (const float*)d_in[20];
    float* out = (float*)d_out;

    float *y, *a, *a2, *qb, *kvb, *ob, *hb, *bb;
    cudaGetSymbolAddress((void**)&y,  g_y);
    cudaGetSymbolAddress((void**)&a,  g_a);
    cudaGetSymbolAddress((void**)&a2, g_a2);
    cudaGetSymbolAddress((void**)&qb, g_q);
    cudaGetSymbolAddress((void**)&kvb,g_kv);
    cudaGetSymbolAddress((void**)&ob, g_o);
    cudaGetSymbolAddress((void**)&hb, g_h);
    cudaGetSymbolAddress((void**)&bb, g_bias);

    const dim3 tgrid(HW/32, CC/32, BB), tblk(32, 8);
    const dim3 g2(2, TOK/128), g4(4, TOK/128), g8(8, TOK/128);

    // embed x1: transpose to (B*HW, C), GEMM, fused pe_ln+n1 -> y (shortcut), a
    transpose_in<<<tgrid, tblk>>>(x1, hb);
    gemm_h<0><<<g2, 256>>>(hb, pe_w, pe_b, nullptr, ob, CC, CC);
    dual_ln<<<TOK, 256>>>(ob, pe_ln_w, pe_ln_b, n1_w, n1_b, y, a);
    // embed x2 -> a2 only
    transpose_in<<<tgrid, tblk>>>(x2, hb);
    gemm_h<0><<<g2, 256>>>(hb, pe_w, pe_b, nullptr, ob, CC, CC);
    dual_ln<<<TOK, 256>>>(ob, pe_ln_w, pe_ln_b, n1_w, n1_b, nullptr, a2);

    // q / kv projections
    gemm_h<0><<<g2, 256>>>(a,  q_w,  q_b,  nullptr, qb,  CC,   CC);
    gemm_h<0><<<g4, 256>>>(a2, kv_w, kv_b, nullptr, kvb, 2*CC, CC);

    // relative position bias + attention
    bias_kernel<<<(NHD*NWT*NWT + 255)/256, 256>>>(relb, bb);
    attn_kernel<<<dim3(WINS, NHD), 64>>>(qb, kvb, bb, ob);

    // proj with residual (in-place on y)
    gemm_h<1><<<g2, 256>>>(ob, proj_w, proj_b, y, y, CC, CC);

    // MLP: LN -> fc1+GELU -> fc2 + residual
    ln_single<<<TOK, 256>>>(y, n2_w, n2_b, a);
    gemm_h<2><<<g8, 256>>>(a,  fc1_w, fc1_b, nullptr, hb, MLPD, CC);
    gemm_h<1><<<g2, 256>>>(hb, fc2_w, fc2_b, y, ob, CC, MLPD);

    // (B, HW, C) -> (B, C, H, W)
    transpose_out<<<tgrid, tblk>>>(ob, out);
}